// round 13
// baseline (speedup 1.0000x reference)
#include <cuda_runtime.h>
#include <stdint.h>

using u64t = unsigned long long;
#define DI __device__ __forceinline__

// ---------------- problem dims ----------------
constexpr int CE = 1024;      // C_emb
constexpr int T_ = 2048;      // T
constexpr int B_ = 16;        // batch
constexpr int KC = 4096;      // codebook size
constexpr int CC = 64;        // C_cb

// ---------------- output layout (float elements) ----------------
constexpr long long OFF_QUANT = 32768;
constexpr long long OFF_LOSS  = OFF_QUANT + (long long)B_ * CE * T_;   // 33587200
constexpr long long OFF_XPROJ = OFF_LOSS + 2;                          // 33587202
constexpr long long OFF_QPROJ = OFF_XPROJ + (long long)B_ * CC * T_;   // 35684354

// ---------------- scratch ----------------
__device__ float g_Win_t[CE * CC];    // [i][o]
__device__ float g_Wout_t[CC * CE];   // [c][o]
__device__ float g_cbn_t[CC * KC];    // [c][k]
__device__ float g_cc2[KC];
__device__ float g_lossP[256];

// ---------------- packed fp32x2 helpers ----------------
DI u64t pack2(float a, float b) {
    u64t r;
    asm("mov.b64 %0, {%1, %2};" : "=l"(r)
        : "r"(__float_as_uint(a)), "r"(__float_as_uint(b)));
    return r;
}
DI float2 unpack2(u64t v) {
    unsigned int lo, hi;
    asm("mov.b64 {%0, %1}, %2;" : "=r"(lo), "=r"(hi) : "l"(v));
    return make_float2(__uint_as_float(lo), __uint_as_float(hi));
}
DI void fma2(u64t& d, u64t a, u64t b) {
    asm("fma.rn.f32x2 %0, %1, %2, %0;" : "+l"(d) : "l"(a), "l"(b));
}
DI u64t add2(u64t a, u64t b) {
    u64t r;
    asm("add.rn.f32x2 %0, %1, %2;" : "=l"(r) : "l"(a), "l"(b));
    return r;
}

// ---------------- cp.async helpers ----------------
DI void cpa16(uint32_t saddr, const void* gptr) {
    asm volatile("cp.async.cg.shared.global [%0], [%1], 16;"
                 :: "r"(saddr), "l"(gptr));
}
DI void cpa8(uint32_t saddr, const void* gptr) {
    asm volatile("cp.async.ca.shared.global [%0], [%1], 8;"
                 :: "r"(saddr), "l"(gptr));
}
DI void cpa_commit() { asm volatile("cp.async.commit_group;"); }
template<int N> DI void cpa_wait() { asm volatile("cp.async.wait_group %0;" :: "n"(N)); }

// ============================================================================
// Kernel 1a: W_in^T
// ============================================================================
__global__ void k_win(const float* __restrict__ v_in, const float* __restrict__ g_in) {
    __shared__ float rb[256];
    int o = blockIdx.x, tid = threadIdx.x;
    float s = 0.f;
    for (int i = tid; i < CE; i += 256) {
        float v = v_in[o * CE + i];
        s = fmaf(v, v, s);
    }
    rb[tid] = s; __syncthreads();
    for (int st = 128; st >= 1; st >>= 1) {
        if (tid < st) rb[tid] += rb[tid + st];
        __syncthreads();
    }
    float nrm = sqrtf(rb[0]);
    float g = g_in[o];
    for (int i = tid; i < CE; i += 256) {
        g_Win_t[i * CC + o] = g * v_in[o * CE + i] / nrm;
    }
}

// ============================================================================
// Kernel 1b: W_out^T
// ============================================================================
__global__ void k_wout(const float* __restrict__ v_out, const float* __restrict__ g_out) {
    int tid = threadIdx.x;
    int o = blockIdx.x * 8 + (tid >> 5);
    int lane = tid & 31;
    float a = v_out[o * CC + lane];
    float b = v_out[o * CC + lane + 32];
    float s = a * a + b * b;
    #pragma unroll
    for (int m = 16; m >= 1; m >>= 1) s += __shfl_xor_sync(0xffffffffu, s, m);
    float nrm = sqrtf(s);
    float g = g_out[o];
    g_Wout_t[lane * CE + o]        = g * a / nrm;
    g_Wout_t[(lane + 32) * CE + o] = g * b / nrm;
}

// ============================================================================
// Kernel 1c: normalized codebook transposed + ||cbn_k||^2
// ============================================================================
__global__ void k_cbn(const float* __restrict__ cbk) {
    __shared__ float s[64 * 65];
    int tid = threadIdx.x;
    int k0 = blockIdx.x * 64;
    for (int e = tid; e < 4096; e += 256) {
        int r = e >> 6, c = e & 63;
        s[r * 65 + c] = cbk[(k0 + r) * CC + c];
    }
    __syncthreads();
    if (tid < 64) {
        int r = tid;
        float ss = 0.f;
        #pragma unroll 8
        for (int c = 0; c < 64; c++) { float v = s[r * 65 + c]; ss = fmaf(v, v, ss); }
        float n = fmaxf(sqrtf(ss), 1e-12f);
        float cc = 0.f;
        #pragma unroll 8
        for (int c = 0; c < 64; c++) {
            float v = s[r * 65 + c] / n;
            s[r * 65 + c] = v;
            cc = fmaf(v, v, cc);
        }
        g_cc2[k0 + r] = cc;
    }
    __syncthreads();
    for (int e = tid; e < 4096; e += 256) {
        int c = e >> 6, r = e & 63;
        g_cbn_t[c * KC + k0 + r] = s[r * 65 + c];
    }
}

// ============================================================================
// Kernel 2: x_proj = W_in @ x — cp.async double-buffered (round-4, 99us)
// ============================================================================
__global__ void __launch_bounds__(256) k_gemm_in(const float* __restrict__ x, float* dout) {
    extern __shared__ float sm[];
    int b = blockIdx.y, tid = threadIdx.x;
    int tg0 = blockIdx.x * 128;
    int o0 = (tid >> 5) * 8;
    int t0 = (tid & 31) * 4;
    const float* xb = x + (long long)b * CE * T_ + tg0;
    uint32_t sbase = (uint32_t)__cvta_generic_to_shared(sm);

    u64t tot[8][2], acc[8][2];
    #pragma unroll
    for (int i = 0; i < 8; i++) { tot[i][0] = 0; tot[i][1] = 0; acc[i][0] = 0; acc[i][1] = 0; }

    {
        const float* wsrc = g_Win_t;
        #pragma unroll
        for (int i = 0; i < 4; i++) {
            int e = tid * 4 + i * 1024;
            cpa16(sbase + e * 4, wsrc + e);
        }
        #pragma unroll
        for (int i = 0; i < 8; i++) {
            int e = tid * 4 + i * 1024;
            cpa16(sbase + 16384 + e * 4, xb + (long long)(e >> 7) * T_ + (e & 127));
        }
        cpa_commit();
    }

    for (int ch = 0; ch < 16; ch++) {
        int buf = ch & 1;
        if (ch < 15) {
            int kt = (ch + 1) * 64;
            uint32_t bb = sbase + (buf ^ 1) * 49152;
            const float* wsrc = g_Win_t + kt * 64;
            #pragma unroll
            for (int i = 0; i < 4; i++) {
                int e = tid * 4 + i * 1024;
                cpa16(bb + e * 4, wsrc + e);
            }
            const float* xsrc = xb + (long long)kt * T_;
            #pragma unroll
            for (int i = 0; i < 8; i++) {
                int e = tid * 4 + i * 1024;
                cpa16(bb + 16384 + e * 4, xsrc + (long long)(e >> 7) * T_ + (e & 127));
            }
            cpa_commit();
            cpa_wait<1>();
        } else {
            cpa_wait<0>();
        }
        __syncthreads();
        const float* sW = sm + buf * 12288;
        const float* sX = sm + buf * 12288 + 4096;

        #pragma unroll 8
        for (int k = 0; k < 64; k++) {
            float4 xa = *(const float4*)&sX[k * 128 + t0];
            u64t xb0 = pack2(xa.x, xa.y), xb1 = pack2(xa.z, xa.w);
            float4 w0 = *(const float4*)&sW[k * 64 + o0];
            float4 w1 = *(const float4*)&sW[k * 64 + o0 + 4];
            float wv[8] = {w0.x, w0.y, w0.z, w0.w, w1.x, w1.y, w1.z, w1.w};
            #pragma unroll
            for (int i = 0; i < 8; i++) {
                u64t wb = pack2(wv[i], wv[i]);
                fma2(acc[i][0], wb, xb0);
                fma2(acc[i][1], wb, xb1);
            }
        }
        #pragma unroll
        for (int i = 0; i < 8; i++) {
            tot[i][0] = add2(tot[i][0], acc[i][0]); acc[i][0] = 0;
            tot[i][1] = add2(tot[i][1], acc[i][1]); acc[i][1] = 0;
        }
        __syncthreads();
    }
    #pragma unroll
    for (int i = 0; i < 8; i++) {
        float2 p0 = unpack2(tot[i][0]);
        float2 p1 = unpack2(tot[i][1]);
        long long base = OFF_XPROJ + (long long)b * CC * T_ + (long long)(o0 + i) * T_ + tg0 + t0;
        *(float2*)&dout[base]     = p0;
        *(float2*)&dout[base + 2] = p1;
    }
}

// ============================================================================
// Kernel 3: scoring + argmin. Zero-pack inner loop.
//  - sed [c][2t]: normalized e duplicated (v,v) — broadcast side, 64KB
//  - scb double-buffered cb chunks [c][k], direct ulonglong2 (adjacent k)
// Accumulation order over c identical to round 1 -> bit-identical codes.
// Dyn smem: 16384 (sed) + 2*4096 (scb) floats = 98304 B.
// ============================================================================
__global__ void __launch_bounds__(256) k_score(float* dout) {
    extern __shared__ float sm[];
    float* sed = sm;                      // [c][2t] 64 x 256
    __shared__ float sinv[128];
    int tid = threadIdx.x;
    int tokg = blockIdx.x * 128;
    int b = tokg >> 11;
    int t0g = tokg & (T_ - 1);
    const float* xp = dout + OFF_XPROJ + (long long)b * CC * T_ + t0g;
    uint32_t sbase = (uint32_t)__cvta_generic_to_shared(sm);

    // load x_proj into even slots of sed
    for (int e = tid; e < 8192; e += 256) {
        int c = e >> 7, t = e & 127;
        sed[c * 256 + 2 * t] = xp[c * T_ + t];
    }
    __syncthreads();
    if (tid < 128) {
        float s = 0.f;
        #pragma unroll 8
        for (int c = 0; c < 64; c++) { float v = sed[c * 256 + 2 * tid]; s = fmaf(v, v, s); }
        sinv[tid] = 1.f / fmaxf(sqrtf(s), 1e-12f);
    }
    __syncthreads();
    // normalize + duplicate
    for (int e = tid; e < 8192; e += 256) {
        int c = e >> 7, t = e & 127;
        float v = sed[c * 256 + 2 * t] * sinv[t];
        sed[c * 256 + 2 * t]     = v;
        sed[c * 256 + 2 * t + 1] = v;
    }

    // prefetch cb chunk 0 (scb buf0 at float offset 16384)
    #pragma unroll
    for (int i = 0; i < 4; i++) {
        int e = tid * 4 + i * 1024;
        cpa16(sbase + (16384 + e) * 4, g_cbn_t + (e >> 6) * KC + (e & 63));
    }
    cpa_commit();

    int ktid = tid & 15, ttid = tid >> 4;
    int to0 = ttid * 8, kk0 = ktid * 4;
    float bestv[8]; int besti[8];
    #pragma unroll
    for (int i = 0; i < 8; i++) { bestv[i] = __int_as_float(0x7f800000); besti[i] = 0; }

    for (int ch = 0; ch < 64; ch++) {
        int buf = ch & 1;
        if (ch < 63) {
            int kc = (ch + 1) * 64;
            uint32_t bb = sbase + (16384 + (buf ^ 1) * 4096) * 4;
            #pragma unroll
            for (int i = 0; i < 4; i++) {
                int e = tid * 4 + i * 1024;
                cpa16(bb + e * 4, g_cbn_t + (e >> 6) * KC + kc + (e & 63));
            }
            cpa_commit();
            cpa_wait<1>();
        } else {
            cpa_wait<0>();
        }
        __syncthreads();
        const float* sc = sm + 16384 + buf * 4096;
        int kc = ch * 64;

        u64t acc[8][2];
        #pragma unroll
        for (int i = 0; i < 8; i++) { acc[i][0] = 0; acc[i][1] = 0; }
        #pragma unroll 8
        for (int c = 0; c < 64; c++) {
            ulonglong2 cb = *(const ulonglong2*)&sc[c * 64 + kk0];          // (k0,k1),(k2,k3)
            ulonglong2 e0 = *(const ulonglong2*)&sed[c * 256 + 2 * to0];     // tok0,tok1 dup
            ulonglong2 e1 = *(const ulonglong2*)&sed[c * 256 + 2 * to0 + 4]; // tok2,tok3
            ulonglong2 e2 = *(const ulonglong2*)&sed[c * 256 + 2 * to0 + 8]; // tok4,tok5
            ulonglong2 e3 = *(const ulonglong2*)&sed[c * 256 + 2 * to0 + 12];// tok6,tok7
            u64t ed[8] = {e0.x, e0.y, e1.x, e1.y, e2.x, e2.y, e3.x, e3.y};
            #pragma unroll
            for (int i = 0; i < 8; i++) {
                fma2(acc[i][0], ed[i], cb.x);
                fma2(acc[i][1], ed[i], cb.y);
            }
        }
        float4 cc = *(const float4*)&g_cc2[kc + kk0];
        #pragma unroll
        for (int i = 0; i < 8; i++) {
            float2 d0 = unpack2(acc[i][0]);
            float2 d1 = unpack2(acc[i][1]);
            float s0 = fmaf(-2.f, d0.x, cc.x);
            float s1 = fmaf(-2.f, d0.y, cc.y);
            float s2 = fmaf(-2.f, d1.x, cc.z);
            float s3 = fmaf(-2.f, d1.y, cc.w);
            int kbase = kc + kk0;
            if (s0 < bestv[i]) { bestv[i] = s0; besti[i] = kbase; }
            if (s1 < bestv[i]) { bestv[i] = s1; besti[i] = kbase + 1; }
            if (s2 < bestv[i]) { bestv[i] = s2; besti[i] = kbase + 2; }
            if (s3 < bestv[i]) { bestv[i] = s3; besti[i] = kbase + 3; }
        }
        __syncthreads();
    }
    float2* red = (float2*)(sm + 16384);  // 16KB across both scb bufs
    #pragma unroll
    for (int i = 0; i < 8; i++)
        red[(to0 + i) * 16 + ktid] = make_float2(bestv[i], __int_as_float(besti[i]));
    __syncthreads();
    if (tid < 128) {
        float bv = __int_as_float(0x7f800000);
        int bi = 0x7fffffff;
        #pragma unroll
        for (int m = 0; m < 16; m++) {
            float2 r = red[tid * 16 + m];
            int ri = __float_as_int(r.y);
            if (r.x < bv || (r.x == bv && ri < bi)) { bv = r.x; bi = ri; }
        }
        dout[tokg + tid] = (float)bi;
    }
}

// ============================================================================
// Kernel 4: gather -> quantized_proj; loss partials.
// ============================================================================
__global__ void k_gather(const float* __restrict__ cbk, float* dout) {
    __shared__ int sidx[128];
    __shared__ float sq[128 * 65];
    __shared__ float rbuf[256];
    int tid = threadIdx.x;
    int tokg = blockIdx.x * 128;
    int b = tokg >> 11;
    int t0g = tokg & (T_ - 1);

    if (tid < 128) sidx[tid] = (int)dout[tokg + tid];
    __syncthreads();
    for (int e = tid; e < 8192; e += 256) {
        int t = e >> 6, c = e & 63;
        sq[t * 65 + c] = cbk[(long long)sidx[t] * CC + c];
    }
    __syncthreads();
    const float* xp = dout + OFF_XPROJ + (long long)b * CC * T_ + t0g;
    float* qp = dout + OFF_QPROJ + (long long)b * CC * T_ + t0g;
    float ls = 0.f;
    for (int e = tid; e < 8192; e += 256) {
        int c = e >> 7, j = e & 127;
        float q = sq[j * 65 + c];
        float d = xp[c * T_ + j] - q;
        ls = fmaf(d, d, ls);
        qp[c * T_ + j] = q;
    }
    rbuf[tid] = ls; __syncthreads();
    for (int st = 128; st >= 1; st >>= 1) {
        if (tid < st) rbuf[tid] += rbuf[tid + st];
        __syncthreads();
    }
    if (tid == 0) g_lossP[blockIdx.x] = rbuf[0];
}

// ============================================================================
// Kernel 5: finalize losses
// ============================================================================
__global__ void k_loss(float* dout) {
    __shared__ float rb[256];
    int tid = threadIdx.x;
    rb[tid] = g_lossP[tid]; __syncthreads();
    for (int st = 128; st >= 1; st >>= 1) {
        if (tid < st) rb[tid] += rb[tid + st];
        __syncthreads();
    }
    if (tid == 0) {
        float L = rb[0] * (1.f / 2097152.f);
        dout[OFF_LOSS] = L;
        dout[OFF_LOSS + 1] = L;
    }
}

// ============================================================================
// Kernel 6: quantized = W_out @ quantized_proj — cp.async fills
// (W 16B aligned; Q region only 8B-aligned -> 8B cp.async). Compute unchanged.
// Dyn smem 48KB: sW 8192 floats, sQ 4096 floats.
// ============================================================================
__global__ void __launch_bounds__(256) k_gemm_out(float* dout) {
    extern __shared__ float sm[];
    float* sW = sm;            // [c][o] 64 x 128
    float* sQ = sm + 8192;     // [c][t] 64 x 64
    int tid = threadIdx.x;
    int b = blockIdx.z;
    int o0g = blockIdx.y * 128;
    int t0g = blockIdx.x * 64;
    uint32_t sbase = (uint32_t)__cvta_generic_to_shared(sm);

    // async fills
    #pragma unroll
    for (int i = 0; i < 8; i++) {
        int e = tid * 4 + i * 1024;
        cpa16(sbase + e * 4, g_Wout_t + (e >> 7) * CE + o0g + (e & 127));
    }
    const float* qp = dout + OFF_QPROJ + (long long)b * CC * T_ + t0g;
    #pragma unroll
    for (int i = 0; i < 8; i++) {
        int e = tid * 2 + i * 512;
        cpa8(sbase + (8192 + e) * 4, qp + (e >> 6) * T_ + (e & 63));
    }
    cpa_commit();
    cpa_wait<0>();
    __syncthreads();

    int ttid = tid & 15, otid = tid >> 4;
    int o0 = otid * 8, t0 = ttid * 4;
    u64t acc[8][2];
    #pragma unroll
    for (int i = 0; i < 8; i++) { acc[i][0] = 0; acc[i][1] = 0; }
    #pragma unroll 8
    for (int c = 0; c < 64; c++) {
        ulonglong2 q = *(const ulonglong2*)&sQ[c * 64 + t0];   // adjacent t pairs
        float4 w0 = *(const float4*)&sW[c * 128 + o0];
        float4 w1 = *(const float4*)&sW[c * 128 + o0 + 4];
        float wv[8] = {w0.x, w0.y, w0.z, w0.w, w1.x, w1.y, w1.z, w1.w};
        #pragma unroll
        for (int i = 0; i < 8; i++) {
            u64t wb = pack2(wv[i], wv[i]);
            fma2(acc[i][0], wb, q.x);
            fma2(acc[i][1], wb, q.y);
        }
    }
    float* outq = dout + OFF_QUANT + (long long)b * CE * T_;
    #pragma unroll
    for (int i = 0; i < 8; i++) {
        float2 a = unpack2(acc[i][0]);
        float2 bb = unpack2(acc[i][1]);
        float4 v = make_float4(a.x, a.y, bb.x, bb.y);
        *(float4*)&outq[(long long)(o0g + o0 + i) * T_ + t0g + t0] = v;
    }
}

// ============================================================================
extern "C" void kernel_launch(void* const* d_in, const int* in_sizes, int n_in,
                              void* d_out, int out_size) {
    const float* x        = (const float*)d_in[0];
    const float* v_in     = (const float*)d_in[1];
    const float* g_in     = (const float*)d_in[2];
    const float* v_out    = (const float*)d_in[3];
    const float* g_out    = (const float*)d_in[4];
    const float* codebook = (const float*)d_in[5];
    float* out = (float*)d_out;

    cudaFuncSetAttribute(k_gemm_in, cudaFuncAttributeMaxDynamicSharedMemorySize, 98304);
    cudaFuncSetAttribute(k_score,   cudaFuncAttributeMaxDynamicSharedMemorySize, 98304);

    k_win <<<64, 256>>>(v_in, g_in);
    k_wout<<<128, 256>>>(v_out, g_out);
    k_cbn <<<64, 256>>>(codebook);
    k_gemm_in<<<dim3(16, 16), 256, 98304>>>(x, out);
    k_score<<<256, 256, 98304>>>(out);
    k_gather<<<256, 256>>>(codebook, out);
    k_loss<<<1, 256>>>(out);
    k_gemm_out<<<dim3(32, 8, 16), 256, 49152>>>(out);
}

// round 14
// speedup vs baseline: 1.2042x; 1.2042x over previous
#include <cuda_runtime.h>
#include <stdint.h>

using u64t = unsigned long long;
#define DI __device__ __forceinline__

// ---------------- problem dims ----------------
constexpr int CE = 1024;      // C_emb
constexpr int T_ = 2048;      // T
constexpr int B_ = 16;        // batch
constexpr int KC = 4096;      // codebook size
constexpr int CC = 64;        // C_cb

// ---------------- output layout (float elements) ----------------
constexpr long long OFF_QUANT = 32768;
constexpr long long OFF_LOSS  = OFF_QUANT + (long long)B_ * CE * T_;   // 33587200
constexpr long long OFF_XPROJ = OFF_LOSS + 2;                          // 33587202
constexpr long long OFF_QPROJ = OFF_XPROJ + (long long)B_ * CC * T_;   // 35684354

// ---------------- scratch ----------------
__device__ float g_Win_t[CE * CC];    // [i][o]
__device__ float g_Wout_t[CC * CE];   // [c][o]
__device__ float g_cbn_t[CC * KC];    // [c][k]
__device__ float g_cc2[KC];
__device__ float g_lossP[256];

// ---------------- packed fp32x2 helpers ----------------
DI u64t pack2(float a, float b) {
    u64t r;
    asm("mov.b64 %0, {%1, %2};" : "=l"(r)
        : "r"(__float_as_uint(a)), "r"(__float_as_uint(b)));
    return r;
}
DI float2 unpack2(u64t v) {
    unsigned int lo, hi;
    asm("mov.b64 {%0, %1}, %2;" : "=r"(lo), "=r"(hi) : "l"(v));
    return make_float2(__uint_as_float(lo), __uint_as_float(hi));
}
DI void fma2(u64t& d, u64t a, u64t b) {
    asm("fma.rn.f32x2 %0, %1, %2, %0;" : "+l"(d) : "l"(a), "l"(b));
}
DI u64t add2(u64t a, u64t b) {
    u64t r;
    asm("add.rn.f32x2 %0, %1, %2;" : "=l"(r) : "l"(a), "l"(b));
    return r;
}

// ---------------- cp.async helpers ----------------
DI void cpa16(uint32_t saddr, const void* gptr) {
    asm volatile("cp.async.cg.shared.global [%0], [%1], 16;"
                 :: "r"(saddr), "l"(gptr));
}
DI void cpa8(uint32_t saddr, const void* gptr) {
    asm volatile("cp.async.ca.shared.global [%0], [%1], 8;"
                 :: "r"(saddr), "l"(gptr));
}
DI void cpa_commit() { asm volatile("cp.async.commit_group;"); }
template<int N> DI void cpa_wait() { asm volatile("cp.async.wait_group %0;" :: "n"(N)); }

// ============================================================================
// Kernel 1a: W_in^T
// ============================================================================
__global__ void k_win(const float* __restrict__ v_in, const float* __restrict__ g_in) {
    __shared__ float rb[256];
    int o = blockIdx.x, tid = threadIdx.x;
    float s = 0.f;
    for (int i = tid; i < CE; i += 256) {
        float v = v_in[o * CE + i];
        s = fmaf(v, v, s);
    }
    rb[tid] = s; __syncthreads();
    for (int st = 128; st >= 1; st >>= 1) {
        if (tid < st) rb[tid] += rb[tid + st];
        __syncthreads();
    }
    float nrm = sqrtf(rb[0]);
    float g = g_in[o];
    for (int i = tid; i < CE; i += 256) {
        g_Win_t[i * CC + o] = g * v_in[o * CE + i] / nrm;
    }
}

// ============================================================================
// Kernel 1b: W_out^T
// ============================================================================
__global__ void k_wout(const float* __restrict__ v_out, const float* __restrict__ g_out) {
    int tid = threadIdx.x;
    int o = blockIdx.x * 8 + (tid >> 5);
    int lane = tid & 31;
    float a = v_out[o * CC + lane];
    float b = v_out[o * CC + lane + 32];
    float s = a * a + b * b;
    #pragma unroll
    for (int m = 16; m >= 1; m >>= 1) s += __shfl_xor_sync(0xffffffffu, s, m);
    float nrm = sqrtf(s);
    float g = g_out[o];
    g_Wout_t[lane * CE + o]        = g * a / nrm;
    g_Wout_t[(lane + 32) * CE + o] = g * b / nrm;
}

// ============================================================================
// Kernel 1c: normalized codebook transposed + ||cbn_k||^2
// ============================================================================
__global__ void k_cbn(const float* __restrict__ cbk) {
    __shared__ float s[64 * 65];
    int tid = threadIdx.x;
    int k0 = blockIdx.x * 64;
    for (int e = tid; e < 4096; e += 256) {
        int r = e >> 6, c = e & 63;
        s[r * 65 + c] = cbk[(k0 + r) * CC + c];
    }
    __syncthreads();
    if (tid < 64) {
        int r = tid;
        float ss = 0.f;
        #pragma unroll 8
        for (int c = 0; c < 64; c++) { float v = s[r * 65 + c]; ss = fmaf(v, v, ss); }
        float n = fmaxf(sqrtf(ss), 1e-12f);
        float cc = 0.f;
        #pragma unroll 8
        for (int c = 0; c < 64; c++) {
            float v = s[r * 65 + c] / n;
            s[r * 65 + c] = v;
            cc = fmaf(v, v, cc);
        }
        g_cc2[k0 + r] = cc;
    }
    __syncthreads();
    for (int e = tid; e < 4096; e += 256) {
        int c = e >> 6, r = e & 63;
        g_cbn_t[c * KC + k0 + r] = s[r * 65 + c];
    }
}

// ============================================================================
// Kernel 2: x_proj = W_in @ x — cp.async double-buffered (round-4, 99us)
// ============================================================================
__global__ void __launch_bounds__(256) k_gemm_in(const float* __restrict__ x, float* dout) {
    extern __shared__ float sm[];
    int b = blockIdx.y, tid = threadIdx.x;
    int tg0 = blockIdx.x * 128;
    int o0 = (tid >> 5) * 8;
    int t0 = (tid & 31) * 4;
    const float* xb = x + (long long)b * CE * T_ + tg0;
    uint32_t sbase = (uint32_t)__cvta_generic_to_shared(sm);

    u64t tot[8][2], acc[8][2];
    #pragma unroll
    for (int i = 0; i < 8; i++) { tot[i][0] = 0; tot[i][1] = 0; acc[i][0] = 0; acc[i][1] = 0; }

    {
        const float* wsrc = g_Win_t;
        #pragma unroll
        for (int i = 0; i < 4; i++) {
            int e = tid * 4 + i * 1024;
            cpa16(sbase + e * 4, wsrc + e);
        }
        #pragma unroll
        for (int i = 0; i < 8; i++) {
            int e = tid * 4 + i * 1024;
            cpa16(sbase + 16384 + e * 4, xb + (long long)(e >> 7) * T_ + (e & 127));
        }
        cpa_commit();
    }

    for (int ch = 0; ch < 16; ch++) {
        int buf = ch & 1;
        if (ch < 15) {
            int kt = (ch + 1) * 64;
            uint32_t bb = sbase + (buf ^ 1) * 49152;
            const float* wsrc = g_Win_t + kt * 64;
            #pragma unroll
            for (int i = 0; i < 4; i++) {
                int e = tid * 4 + i * 1024;
                cpa16(bb + e * 4, wsrc + e);
            }
            const float* xsrc = xb + (long long)kt * T_;
            #pragma unroll
            for (int i = 0; i < 8; i++) {
                int e = tid * 4 + i * 1024;
                cpa16(bb + 16384 + e * 4, xsrc + (long long)(e >> 7) * T_ + (e & 127));
            }
            cpa_commit();
            cpa_wait<1>();
        } else {
            cpa_wait<0>();
        }
        __syncthreads();
        const float* sW = sm + buf * 12288;
        const float* sX = sm + buf * 12288 + 4096;

        #pragma unroll 8
        for (int k = 0; k < 64; k++) {
            float4 xa = *(const float4*)&sX[k * 128 + t0];
            u64t xb0 = pack2(xa.x, xa.y), xb1 = pack2(xa.z, xa.w);
            float4 w0 = *(const float4*)&sW[k * 64 + o0];
            float4 w1 = *(const float4*)&sW[k * 64 + o0 + 4];
            float wv[8] = {w0.x, w0.y, w0.z, w0.w, w1.x, w1.y, w1.z, w1.w};
            #pragma unroll
            for (int i = 0; i < 8; i++) {
                u64t wb = pack2(wv[i], wv[i]);
                fma2(acc[i][0], wb, xb0);
                fma2(acc[i][1], wb, xb1);
            }
        }
        #pragma unroll
        for (int i = 0; i < 8; i++) {
            tot[i][0] = add2(tot[i][0], acc[i][0]); acc[i][0] = 0;
            tot[i][1] = add2(tot[i][1], acc[i][1]); acc[i][1] = 0;
        }
        __syncthreads();
    }
    #pragma unroll
    for (int i = 0; i < 8; i++) {
        float2 p0 = unpack2(tot[i][0]);
        float2 p1 = unpack2(tot[i][1]);
        long long base = OFF_XPROJ + (long long)b * CC * T_ + (long long)(o0 + i) * T_ + tg0 + t0;
        *(float2*)&dout[base]     = p0;
        *(float2*)&dout[base + 2] = p1;
    }
}

// ============================================================================
// Kernel 3: scoring + argmin — ROUND-4 CHAMPION VERBATIM (64KB, 3 CTAs/SM).
// Dyn smem 64KB: se 8192 floats; scb bufs at 8192 + buf*4096.
// ============================================================================
__global__ void __launch_bounds__(256) k_score(float* dout) {
    extern __shared__ float sm[];
    float* se = sm;                      // [c][t] 64x128
    __shared__ float sinv[128];
    int tid = threadIdx.x;
    int tokg = blockIdx.x * 128;
    int b = tokg >> 11;
    int t0g = tokg & (T_ - 1);
    const float* xp = dout + OFF_XPROJ + (long long)b * CC * T_ + t0g;
    uint32_t sbase = (uint32_t)__cvta_generic_to_shared(sm);

    for (int e = tid; e < 8192; e += 256) {
        int c = e >> 7, t = e & 127;
        se[e] = xp[c * T_ + t];
    }
    __syncthreads();
    if (tid < 128) {
        float s = 0.f;
        #pragma unroll 8
        for (int c = 0; c < 64; c++) { float v = se[c * 128 + tid]; s = fmaf(v, v, s); }
        sinv[tid] = 1.f / fmaxf(sqrtf(s), 1e-12f);
    }
    __syncthreads();
    for (int e = tid; e < 8192; e += 256) se[e] *= sinv[e & 127];
    // no sync needed before prefetch (prefetch writes scb region only)

    // prefetch cb chunk 0
    #pragma unroll
    for (int i = 0; i < 4; i++) {
        int e = tid * 4 + i * 1024;
        cpa16(sbase + (8192 + e) * 4, g_cbn_t + (e >> 6) * KC + (e & 63));
    }
    cpa_commit();

    int ktid = tid & 15, ttid = tid >> 4;
    int to0 = ttid * 8, kk0 = ktid * 4;
    float bestv[8]; int besti[8];
    #pragma unroll
    for (int i = 0; i < 8; i++) { bestv[i] = __int_as_float(0x7f800000); besti[i] = 0; }

    for (int ch = 0; ch < 64; ch++) {
        int buf = ch & 1;
        if (ch < 63) {
            int kc = (ch + 1) * 64;
            uint32_t bb = sbase + (8192 + (buf ^ 1) * 4096) * 4;
            #pragma unroll
            for (int i = 0; i < 4; i++) {
                int e = tid * 4 + i * 1024;
                cpa16(bb + e * 4, g_cbn_t + (e >> 6) * KC + kc + (e & 63));
            }
            cpa_commit();
            cpa_wait<1>();
        } else {
            cpa_wait<0>();
        }
        __syncthreads();
        const float* sc = sm + 8192 + buf * 4096;
        int kc = ch * 64;

        u64t acc[8][2];
        #pragma unroll
        for (int i = 0; i < 8; i++) { acc[i][0] = 0; acc[i][1] = 0; }
        #pragma unroll 8
        for (int c = 0; c < 64; c++) {
            float4 cbv = *(const float4*)&sc[c * 64 + kk0];
            u64t cb0 = pack2(cbv.x, cbv.y), cb1 = pack2(cbv.z, cbv.w);
            float4 e0 = *(const float4*)&se[c * 128 + to0];
            float4 e1 = *(const float4*)&se[c * 128 + to0 + 4];
            float ev[8] = {e0.x, e0.y, e0.z, e0.w, e1.x, e1.y, e1.z, e1.w};
            #pragma unroll
            for (int i = 0; i < 8; i++) {
                u64t eb = pack2(ev[i], ev[i]);
                fma2(acc[i][0], eb, cb0);
                fma2(acc[i][1], eb, cb1);
            }
        }
        float4 cc = *(const float4*)&g_cc2[kc + kk0];
        #pragma unroll
        for (int i = 0; i < 8; i++) {
            float2 d0 = unpack2(acc[i][0]);
            float2 d1 = unpack2(acc[i][1]);
            float s0 = fmaf(-2.f, d0.x, cc.x);
            float s1 = fmaf(-2.f, d0.y, cc.y);
            float s2 = fmaf(-2.f, d1.x, cc.z);
            float s3 = fmaf(-2.f, d1.y, cc.w);
            int kbase = kc + kk0;
            if (s0 < bestv[i]) { bestv[i] = s0; besti[i] = kbase; }
            if (s1 < bestv[i]) { bestv[i] = s1; besti[i] = kbase + 1; }
            if (s2 < bestv[i]) { bestv[i] = s2; besti[i] = kbase + 2; }
            if (s3 < bestv[i]) { bestv[i] = s3; besti[i] = kbase + 3; }
        }
        __syncthreads();   // protect buf before re-prefetch
    }
    float2* red = (float2*)(sm + 8192);  // 16KB over both scb bufs
    #pragma unroll
    for (int i = 0; i < 8; i++)
        red[(to0 + i) * 16 + ktid] = make_float2(bestv[i], __int_as_float(besti[i]));
    __syncthreads();
    if (tid < 128) {
        float bv = __int_as_float(0x7f800000);
        int bi = 0x7fffffff;
        #pragma unroll
        for (int m = 0; m < 16; m++) {
            float2 r = red[tid * 16 + m];
            int ri = __float_as_int(r.y);
            if (r.x < bv || (r.x == bv && ri < bi)) { bv = r.x; bi = ri; }
        }
        dout[tokg + tid] = (float)bi;
    }
}

// ============================================================================
// Kernel 4: gather -> quantized_proj; loss partials.
// ============================================================================
__global__ void k_gather(const float* __restrict__ cbk, float* dout) {
    __shared__ int sidx[128];
    __shared__ float sq[128 * 65];
    __shared__ float rbuf[256];
    int tid = threadIdx.x;
    int tokg = blockIdx.x * 128;
    int b = tokg >> 11;
    int t0g = tokg & (T_ - 1);

    if (tid < 128) sidx[tid] = (int)dout[tokg + tid];
    __syncthreads();
    for (int e = tid; e < 8192; e += 256) {
        int t = e >> 6, c = e & 63;
        sq[t * 65 + c] = cbk[(long long)sidx[t] * CC + c];
    }
    __syncthreads();
    const float* xp = dout + OFF_XPROJ + (long long)b * CC * T_ + t0g;
    float* qp = dout + OFF_QPROJ + (long long)b * CC * T_ + t0g;
    float ls = 0.f;
    for (int e = tid; e < 8192; e += 256) {
        int c = e >> 7, j = e & 127;
        float q = sq[j * 65 + c];
        float d = xp[c * T_ + j] - q;
        ls = fmaf(d, d, ls);
        qp[c * T_ + j] = q;
    }
    rbuf[tid] = ls; __syncthreads();
    for (int st = 128; st >= 1; st >>= 1) {
        if (tid < st) rbuf[tid] += rbuf[tid + st];
        __syncthreads();
    }
    if (tid == 0) g_lossP[blockIdx.x] = rbuf[0];
}

// ============================================================================
// Kernel 5: finalize losses
// ============================================================================
__global__ void k_loss(float* dout) {
    __shared__ float rb[256];
    int tid = threadIdx.x;
    rb[tid] = g_lossP[tid]; __syncthreads();
    for (int st = 128; st >= 1; st >>= 1) {
        if (tid < st) rb[tid] += rb[tid + st];
        __syncthreads();
    }
    if (tid == 0) {
        float L = rb[0] * (1.f / 2097152.f);
        dout[OFF_LOSS] = L;
        dout[OFF_LOSS + 1] = L;
    }
}

// ============================================================================
// Kernel 6: quantized = W_out @ quantized_proj — cp.async fills (round-13)
// ============================================================================
__global__ void __launch_bounds__(256) k_gemm_out(float* dout) {
    extern __shared__ float sm[];
    float* sW = sm;            // [c][o] 64 x 128
    float* sQ = sm + 8192;     // [c][t] 64 x 64
    int tid = threadIdx.x;
    int b = blockIdx.z;
    int o0g = blockIdx.y * 128;
    int t0g = blockIdx.x * 64;
    uint32_t sbase = (uint32_t)__cvta_generic_to_shared(sm);

    // async fills
    #pragma unroll
    for (int i = 0; i < 8; i++) {
        int e = tid * 4 + i * 1024;
        cpa16(sbase + e * 4, g_Wout_t + (e >> 7) * CE + o0g + (e & 127));
    }
    const float* qp = dout + OFF_QPROJ + (long long)b * CC * T_ + t0g;
    #pragma unroll
    for (int i = 0; i < 8; i++) {
        int e = tid * 2 + i * 512;
        cpa8(sbase + (8192 + e) * 4, qp + (e >> 6) * T_ + (e & 63));
    }
    cpa_commit();
    cpa_wait<0>();
    __syncthreads();

    int ttid = tid & 15, otid = tid >> 4;
    int o0 = otid * 8, t0 = ttid * 4;
    u64t acc[8][2];
    #pragma unroll
    for (int i = 0; i < 8; i++) { acc[i][0] = 0; acc[i][1] = 0; }
    #pragma unroll 8
    for (int c = 0; c < 64; c++) {
        ulonglong2 q = *(const ulonglong2*)&sQ[c * 64 + t0];   // adjacent t pairs
        float4 w0 = *(const float4*)&sW[c * 128 + o0];
        float4 w1 = *(const float4*)&sW[c * 128 + o0 + 4];
        float wv[8] = {w0.x, w0.y, w0.z, w0.w, w1.x, w1.y, w1.z, w1.w};
        #pragma unroll
        for (int i = 0; i < 8; i++) {
            u64t wb = pack2(wv[i], wv[i]);
            fma2(acc[i][0], wb, q.x);
            fma2(acc[i][1], wb, q.y);
        }
    }
    float* outq = dout + OFF_QUANT + (long long)b * CE * T_;
    #pragma unroll
    for (int i = 0; i < 8; i++) {
        float2 a = unpack2(acc[i][0]);
        float2 bb = unpack2(acc[i][1]);
        float4 v = make_float4(a.x, a.y, bb.x, bb.y);
        *(float4*)&outq[(long long)(o0g + o0 + i) * T_ + t0g + t0] = v;
    }
}

// ============================================================================
extern "C" void kernel_launch(void* const* d_in, const int* in_sizes, int n_in,
                              void* d_out, int out_size) {
    const float* x        = (const float*)d_in[0];
    const float* v_in     = (const float*)d_in[1];
    const float* g_in     = (const float*)d_in[2];
    const float* v_out    = (const float*)d_in[3];
    const float* g_out    = (const float*)d_in[4];
    const float* codebook = (const float*)d_in[5];
    float* out = (float*)d_out;

    cudaFuncSetAttribute(k_gemm_in, cudaFuncAttributeMaxDynamicSharedMemorySize, 98304);
    cudaFuncSetAttribute(k_score,   cudaFuncAttributeMaxDynamicSharedMemorySize, 65536);

    k_win <<<64, 256>>>(v_in, g_in);
    k_wout<<<128, 256>>>(v_out, g_out);
    k_cbn <<<64, 256>>>(codebook);
    k_gemm_in<<<dim3(16, 16), 256, 98304>>>(x, out);
    k_score<<<256, 256, 65536>>>(out);
    k_gather<<<256, 256>>>(codebook, out);
    k_loss<<<1, 256>>>(out);
    k_gemm_out<<<dim3(32, 8, 16), 256, 49152>>>(out);
}